// round 6
// baseline (speedup 1.0000x reference)
#include <cuda_runtime.h>
#include <cuda_fp16.h>
#include <cstdint>

// ---------------------------------------------------------------------------
// GraphSAGE (2x SAGEConv mean-agg + ReLU) + classifier, fp16 HMMA edition.
//   C = (Ah + Al) @ W_fp16  (A hi/lo split as K-expansion, W quantized once)
// 8-kernel pipeline:
//   1 k_front       : count_deg + convertX(hi/lo) + prepW      (fused)
//   2 k_scan_single : exclusive scan of deg, 1 block            (replaces 3)
//   3 k_scatter     : CSR fill + re-zero deg for next replay    (fused)
//   4 k_agg         : layer-1 mean gather (hi-only)
//   5 k_gemm layer1
//   6 k_agg         : layer-2 mean gather
//   7 k_gemm layer2
//   8 k_gemm classifier
// ---------------------------------------------------------------------------

#define NN 100000
#define NE 1600000
#define F 128
#define MROWS 100096  // 782 * 128

// ------------------------- device scratch ---------------------------------
__device__ int g_deg[NN];         // zero at start of every graph replay (see k_scatter)
__device__ int g_rowoff[NN + 1];
__device__ int g_cursor[NN];
__device__ int g_csr[NE];
__device__ __half g_A1[(size_t)MROWS * 512];  // [Xh|Xl|Gh|Gl]; reused as classifier A' (stride 256)
__device__ __half g_A2[(size_t)MROWS * 512];  // [Hh|Hl|Gh|Gl]
__device__ __half g_B1[128 * 256];            // [Ws1|Wn1] n-major
__device__ __half g_B2[128 * 256];            // [Ws2|Wn2]
__device__ __half g_Bc[64 * 128];             // Wo

// chunk tables
__constant__ int c_aL[8] = {0, 1, 2, 3, 4, 5, 6, 7};
__constant__ int c_bL[8] = {0, 1, 0, 1, 2, 3, 2, 3};
__constant__ int c_aK[4] = {0, 1, 2, 3};
__constant__ int c_bK[4] = {0, 1, 0, 1};

// ------------------------- PTX helpers ------------------------------------
__device__ __forceinline__ uint32_t smem_u32(const void* p) {
    uint32_t a;
    asm("{ .reg .u64 t; cvta.to.shared.u64 t, %1; cvt.u32.u64 %0, t; }"
        : "=r"(a) : "l"(p));
    return a;
}
__device__ __forceinline__ void cp16(uint32_t s, const void* g) {
    asm volatile("cp.async.cg.shared.global [%0], [%1], 16;" :: "r"(s), "l"(g) : "memory");
}
#define CP_COMMIT() asm volatile("cp.async.commit_group;" ::: "memory")
#define CP_WAIT(n)  asm volatile("cp.async.wait_group %0;" :: "n"(n) : "memory")

__device__ __forceinline__ void ldmx4(uint32_t a, uint32_t& r0, uint32_t& r1,
                                      uint32_t& r2, uint32_t& r3) {
    asm volatile("ldmatrix.sync.aligned.m8n8.x4.shared.b16 {%0,%1,%2,%3}, [%4];"
                 : "=r"(r0), "=r"(r1), "=r"(r2), "=r"(r3) : "r"(a));
}
__device__ __forceinline__ void mma16816(float* c, uint32_t a0, uint32_t a1,
                                         uint32_t a2, uint32_t a3,
                                         uint32_t b0, uint32_t b1) {
    asm volatile("mma.sync.aligned.m16n8k16.row.col.f32.f16.f16.f32 "
                 "{%0,%1,%2,%3}, {%4,%5,%6,%7}, {%8,%9}, {%0,%1,%2,%3};"
                 : "+f"(c[0]), "+f"(c[1]), "+f"(c[2]), "+f"(c[3])
                 : "r"(a0), "r"(a1), "r"(a2), "r"(a3), "r"(b0), "r"(b1));
}
__device__ __forceinline__ void split2(float v0, float v1, uint32_t& hi, uint32_t& lo) {
    __half h0 = __float2half_rn(v0), h1 = __float2half_rn(v1);
    __half l0 = __float2half_rn(v0 - __half2float(h0));
    __half l1 = __float2half_rn(v1 - __half2float(h1));
    __half2 hh = __halves2half2(h0, h1), ll = __halves2half2(l0, l1);
    hi = *reinterpret_cast<uint32_t*>(&hh);
    lo = *reinterpret_cast<uint32_t*>(&ll);
}

// ------------------------- 1) fused front kernel ---------------------------
// count_deg (idx < NE) + convertX (idx < NN*32) + prepW (idx < 16384)
__global__ void k_front(const int* __restrict__ dst,
                        const float* __restrict__ x, __half* __restrict__ A,
                        const float* __restrict__ Ws1, const float* __restrict__ Wn1,
                        const float* __restrict__ Ws2, const float* __restrict__ Wn2,
                        const float* __restrict__ Wo) {
    int idx = blockIdx.x * blockDim.x + threadIdx.x;
    if (idx < NE) atomicAdd(&g_deg[dst[idx]], 1);
    if (idx < NN * 32) {
        int row = idx >> 5;
        int c = (idx & 31) << 2;
        float4 v = *reinterpret_cast<const float4*>(x + (size_t)row * F + c);
        uint2 hi, lo;
        split2(v.x, v.y, hi.x, lo.x);
        split2(v.z, v.w, hi.y, lo.y);
        *reinterpret_cast<uint2*>(A + (size_t)row * 512 + c) = hi;        // Xh
        *reinterpret_cast<uint2*>(A + (size_t)row * 512 + 128 + c) = lo;  // Xl
    }
    if (idx < 16384) {
        int k = idx >> 7, n = idx & 127;
        g_B1[n * 256 + k]       = __float2half_rn(Ws1[k * 128 + n]);
        g_B1[n * 256 + 128 + k] = __float2half_rn(Wn1[k * 128 + n]);
        g_B2[n * 256 + k]       = __float2half_rn(Ws2[k * 128 + n]);
        g_B2[n * 256 + 128 + k] = __float2half_rn(Wn2[k * 128 + n]);
        if (n < 64) g_Bc[n * 128 + k] = __float2half_rn(Wo[k * 64 + n]);
    }
}

// ------------------------- 2) single-block scan ----------------------------
__global__ __launch_bounds__(1024) void k_scan_single(int n) {
    __shared__ int s[1024];
    const int CH = (n + 1023) / 1024;     // 98
    const int tid = threadIdx.x;
    const int base = tid * CH;
    int sum = 0;
    for (int j = 0; j < CH; j++) {
        int i = base + j;
        if (i < n) sum += __ldg(&g_deg[i]);
    }
    s[tid] = sum;
    __syncthreads();
#pragma unroll
    for (int off = 1; off < 1024; off <<= 1) {
        int t = (tid >= off) ? s[tid - off] : 0;
        __syncthreads();
        s[tid] += t;
        __syncthreads();
    }
    int run = s[tid] - sum;               // exclusive prefix of this chunk
    for (int j = 0; j < CH; j++) {
        int i = base + j;
        if (i < n) {
            g_rowoff[i] = run;
            g_cursor[i] = run;
            run += __ldg(&g_deg[i]);
        }
    }
    if (tid == 1023) g_rowoff[n] = run;   // sentinel (= NE)
}

// ------------------------- 3) scatter + deg re-zero -------------------------
__global__ void k_scatter(const int* __restrict__ src, const int* __restrict__ dst, int e) {
    int i = blockIdx.x * blockDim.x + threadIdx.x;
    if (i < e) {
        int d = dst[i];
        int pos = atomicAdd(&g_cursor[d], 1);
        g_csr[pos] = src[i];
    }
    if (i < NN) g_deg[i] = 0;  // clean for the next graph replay (zero-init on 1st)
}

// ------------------------- 4/6) aggregation (warp per node, hi-only) -------
// Reads hi block (offset 0, stride 512) of Hsrc; fp32 accumulate;
// writes hi/lo split of mean to cols 256/384 of Adst (stride 512).
__global__ void k_agg(const __half* __restrict__ Hsrc, __half* __restrict__ Adst) {
    int node = (blockIdx.x * blockDim.x + threadIdx.x) >> 5;
    if (node >= NN) return;
    int lane = threadIdx.x & 31;
    int start = __ldg(&g_rowoff[node]);
    int cnt = __ldg(&g_rowoff[node + 1]) - start;
    float a0 = 0.f, a1 = 0.f, a2 = 0.f, a3 = 0.f;
    for (int j = 0; j < cnt; j += 32) {
        int myi = (j + lane < cnt) ? __ldg(&g_csr[start + j + lane]) : 0;
        int nj = min(32, cnt - j);
        int k = 0;
        for (; k + 4 <= nj; k += 4) {
            int s0 = __shfl_sync(0xffffffffu, myi, k);
            int s1 = __shfl_sync(0xffffffffu, myi, k + 1);
            int s2 = __shfl_sync(0xffffffffu, myi, k + 2);
            int s3 = __shfl_sync(0xffffffffu, myi, k + 3);
            uint2 u0 = *reinterpret_cast<const uint2*>(Hsrc + (size_t)s0 * 512 + (lane << 2));
            uint2 u1 = *reinterpret_cast<const uint2*>(Hsrc + (size_t)s1 * 512 + (lane << 2));
            uint2 u2 = *reinterpret_cast<const uint2*>(Hsrc + (size_t)s2 * 512 + (lane << 2));
            uint2 u3 = *reinterpret_cast<const uint2*>(Hsrc + (size_t)s3 * 512 + (lane << 2));
            float2 p0 = __half22float2(*reinterpret_cast<__half2*>(&u0.x));
            float2 p1 = __half22float2(*reinterpret_cast<__half2*>(&u0.y));
            float2 q0 = __half22float2(*reinterpret_cast<__half2*>(&u1.x));
            float2 q1 = __half22float2(*reinterpret_cast<__half2*>(&u1.y));
            float2 r0 = __half22float2(*reinterpret_cast<__half2*>(&u2.x));
            float2 r1 = __half22float2(*reinterpret_cast<__half2*>(&u2.y));
            float2 t0 = __half22float2(*reinterpret_cast<__half2*>(&u3.x));
            float2 t1 = __half22float2(*reinterpret_cast<__half2*>(&u3.y));
            a0 += (p0.x + q0.x) + (r0.x + t0.x);
            a1 += (p0.y + q0.y) + (r0.y + t0.y);
            a2 += (p1.x + q1.x) + (r1.x + t1.x);
            a3 += (p1.y + q1.y) + (r1.y + t1.y);
        }
        for (; k < nj; k++) {
            int s = __shfl_sync(0xffffffffu, myi, k);
            uint2 u = *reinterpret_cast<const uint2*>(Hsrc + (size_t)s * 512 + (lane << 2));
            float2 p0 = __half22float2(*reinterpret_cast<__half2*>(&u.x));
            float2 p1 = __half22float2(*reinterpret_cast<__half2*>(&u.y));
            a0 += p0.x; a1 += p0.y; a2 += p1.x; a3 += p1.y;
        }
    }
    float inv = (cnt > 0) ? (1.0f / (float)cnt) : 1.0f;
    a0 *= inv; a1 *= inv; a2 *= inv; a3 *= inv;
    uint2 hi, lo;
    split2(a0, a1, hi.x, lo.x);
    split2(a2, a3, hi.y, lo.y);
    *reinterpret_cast<uint2*>(Adst + (size_t)node * 512 + 256 + (lane << 2)) = hi;
    *reinterpret_cast<uint2*>(Adst + (size_t)node * 512 + 384 + (lane << 2)) = lo;
}

// ------------------------- warp-MMA GEMM -----------------------------------
// D[128, N] = sum over NIT K=64 chunks of A_chunk @ B_chunk^T, bias (+relu).
// B' (NBCH chunks) fully resident in smem; A double-buffered.
// EPI: 1 = relu, fp16 hi/lo to outA (row stride OSTR, lo at +128)
//      2 = none, fp32 to outF (row stride 64)
template <int N, int NIT, int NBCH, int ASTR, int BSTR, int EPI, int OSTR>
__global__ __launch_bounds__(256) void k_gemm_mma(
    const __half* __restrict__ A, const __half* __restrict__ B,
    const float* __restrict__ bias, float* __restrict__ outF,
    __half* __restrict__ outA, int M)
{
    constexpr int WM = (N == 128) ? 2 : 1;
    constexpr int AT = 128 * 128;        // bytes per A stage
    constexpr int BT = N * 128;          // bytes per B chunk
    extern __shared__ char smem[];
    float* s_bias = reinterpret_cast<float*>(smem);
    const uint32_t sA0 = smem_u32(smem + 512);
    const uint32_t sB0 = sA0 + 2 * AT;

    const int tid = threadIdx.x;
    const int wid = tid >> 5, lane = tid & 31;
    const int wm = (N == 128) ? (wid >> 1) : wid;
    const int wn = (N == 128) ? (wid & 1) : 0;
    const int row0 = blockIdx.x * 128;

    if (tid < N) s_bias[tid] = bias[tid];

    const int* aC = (NIT == 8) ? c_aL : c_aK;
    const int* bC = (NIT == 8) ? c_bL : c_bK;
    const char* Ab = reinterpret_cast<const char*>(A);
    const char* Bb = reinterpret_cast<const char*>(B);
    const int g = lane >> 3, lr = lane & 7;

    float acc[WM][8][4];
#pragma unroll
    for (int i = 0; i < WM; i++)
#pragma unroll
        for (int j = 0; j < 8; j++)
#pragma unroll
            for (int k = 0; k < 4; k++) acc[i][j][k] = 0.f;

    auto load_A = [&](int i) {
        const uint32_t sa = sA0 + (i & 1) * AT;
        const int ca = aC[i];
#pragma unroll
        for (int t = 0; t < 4; t++) {
            int idx = tid + t * 256;
            int m = idx >> 3, u = idx & 7;
            int r = row0 + m; if (r >= M) r = M - 1;
            cp16(sa + m * 128 + ((u ^ (m & 7)) << 4),
                 Ab + ((size_t)r * ASTR + ca * 64 + u * 8) * 2);
        }
        CP_COMMIT();
    };

    // prologue: all of B, committed together with A chunk 0
    {
        constexpr int TOT = NBCH * N * 8;
#pragma unroll
        for (int t = 0; t < TOT / 256; t++) {
            int idx = tid + t * 256;
            int ch = idx / (N * 8);
            int rem = idx % (N * 8);
            int n = rem >> 3, u = rem & 7;
            cp16(sB0 + ch * BT + n * 128 + ((u ^ (n & 7)) << 4),
                 Bb + ((size_t)n * BSTR + ch * 64 + u * 8) * 2);
        }
    }
    load_A(0);

    for (int i = 0; i < NIT; i++) {
        if (i + 1 < NIT) { load_A(i + 1); CP_WAIT(1); }
        else { CP_WAIT(0); }
        __syncthreads();
        const uint32_t sa = sA0 + (i & 1) * AT;
        const uint32_t sbb = sB0 + bC[i] * BT;
#pragma unroll
        for (int kk = 0; kk < 4; kk++) {
            uint32_t a[WM][4];
#pragma unroll
            for (int mt = 0; mt < WM; mt++) {
                int row = wm * (WM * 16) + mt * 16 + (g & 1) * 8 + lr;
                int u = kk * 2 + (g >> 1);
                ldmx4(sa + row * 128 + ((u ^ (row & 7)) << 4),
                      a[mt][0], a[mt][1], a[mt][2], a[mt][3]);
            }
            uint32_t b[4][4];
#pragma unroll
            for (int j = 0; j < 4; j++) {
                int n = wn * 64 + j * 16 + (g >> 1) * 8 + lr;
                int u = kk * 2 + (g & 1);
                ldmx4(sbb + n * 128 + ((u ^ (n & 7)) << 4),
                      b[j][0], b[j][1], b[j][2], b[j][3]);
            }
#pragma unroll
            for (int mt = 0; mt < WM; mt++)
#pragma unroll
                for (int nt = 0; nt < 8; nt++)
                    mma16816(acc[mt][nt],
                             a[mt][0], a[mt][1], a[mt][2], a[mt][3],
                             b[nt >> 1][(nt & 1) * 2], b[nt >> 1][(nt & 1) * 2 + 1]);
        }
        __syncthreads();
    }

    // epilogue
    const int qr = lane >> 2, qc = (lane & 3) << 1;
#pragma unroll
    for (int mt = 0; mt < WM; mt++) {
#pragma unroll
        for (int h = 0; h < 2; h++) {
            int row = row0 + wm * (WM * 16) + mt * 16 + h * 8 + qr;
            if (row >= M) continue;
#pragma unroll
            for (int nt = 0; nt < 8; nt++) {
                int col = wn * 64 + nt * 8 + qc;
                float v0 = acc[mt][nt][h * 2 + 0] + s_bias[col];
                float v1 = acc[mt][nt][h * 2 + 1] + s_bias[col + 1];
                if (EPI == 1) {
                    v0 = fmaxf(v0, 0.f); v1 = fmaxf(v1, 0.f);
                    uint32_t hi, lo;
                    split2(v0, v1, hi, lo);
                    *reinterpret_cast<uint32_t*>(outA + (size_t)row * OSTR + col) = hi;
                    *reinterpret_cast<uint32_t*>(outA + (size_t)row * OSTR + 128 + col) = lo;
                } else {
                    float2 f2 = {v0, v1};
                    *reinterpret_cast<float2*>(outF + (size_t)row * 64 + col) = f2;
                }
            }
        }
    }
}

// ------------------------- launch ------------------------------------------
extern "C" void kernel_launch(void* const* d_in, const int* in_sizes, int n_in,
                              void* d_out, int out_size) {
    const float* x       = (const float*)d_in[0];
    const float* Wself1  = (const float*)d_in[1];
    const float* Wneigh1 = (const float*)d_in[2];
    const float* b1      = (const float*)d_in[3];
    const float* Wself2  = (const float*)d_in[4];
    const float* Wneigh2 = (const float*)d_in[5];
    const float* b2      = (const float*)d_in[6];
    const float* Wout    = (const float*)d_in[7];
    const float* bout    = (const float*)d_in[8];
    const int* edge_src  = (const int*)d_in[9];
    const int* edge_dst  = (const int*)d_in[10];
    float* out = (float*)d_out;

    const int M = in_sizes[0] / F;      // 100000
    const int E = in_sizes[9];          // 1600000
    const int GB = (M + 127) / 128;     // 782
    const int AGGB = (M * 32 + 255) / 256;
    const int FRONTB = (NN * 32 + 255) / 256;   // covers NE and 16384 too

    __half *A1, *A2, *B1, *B2, *Bc;
    cudaGetSymbolAddress((void**)&A1, g_A1);
    cudaGetSymbolAddress((void**)&A2, g_A2);
    cudaGetSymbolAddress((void**)&B1, g_B1);
    cudaGetSymbolAddress((void**)&B2, g_B2);
    cudaGetSymbolAddress((void**)&Bc, g_Bc);

    const int SMEM_L = 512 + 2 * 16384 + 4 * 128 * 128;  // 98816
    const int SMEM_C = 512 + 2 * 16384 + 2 * 64 * 128;   // 49664
    cudaFuncSetAttribute((const void*)k_gemm_mma<128, 8, 4, 512, 256, 1, 512>,
                         cudaFuncAttributeMaxDynamicSharedMemorySize, SMEM_L);
    cudaFuncSetAttribute((const void*)k_gemm_mma<128, 8, 4, 512, 256, 1, 256>,
                         cudaFuncAttributeMaxDynamicSharedMemorySize, SMEM_L);
    cudaFuncSetAttribute((const void*)k_gemm_mma<64, 4, 2, 256, 128, 2, 0>,
                         cudaFuncAttributeMaxDynamicSharedMemorySize, SMEM_C);

    // 1) fused: degree count + X hi/lo convert + weight prep
    k_front<<<FRONTB, 256>>>(edge_dst, x, A1, Wself1, Wneigh1, Wself2, Wneigh2, Wout);
    // 2) exclusive scan (single block)
    k_scan_single<<<1, 1024>>>(M);
    // 3) CSR scatter + deg re-zero for next replay
    k_scatter<<<(E + 255) / 256, 256>>>(edge_src, edge_dst, E);
    // 4) layer-1 aggregation (gather Xh from A1, write G blocks of A1)
    k_agg<<<AGGB, 256>>>(A1, A1);
    // 5) layer-1 GEMM -> A2 [Hh|Hl]
    k_gemm_mma<128, 8, 4, 512, 256, 1, 512><<<GB, 256, SMEM_L>>>(A1, B1, b1, nullptr, A2, M);
    // 6) layer-2 aggregation (gather Hh from A2, write G blocks of A2)
    k_agg<<<AGGB, 256>>>(A2, A2);
    // 7) layer-2 GEMM -> classifier A' in A1 (stride 256)
    k_gemm_mma<128, 8, 4, 512, 256, 1, 256><<<GB, 256, SMEM_L>>>(A2, B2, b2, nullptr, A1, M);
    // 8) classifier
    k_gemm_mma<64, 4, 2, 256, 128, 2, 0><<<GB, 256, SMEM_C>>>(A1, Bc, bout, out, nullptr, M);
}

// round 7
// speedup vs baseline: 1.5447x; 1.5447x over previous
#include <cuda_runtime.h>
#include <cuda_fp16.h>
#include <cstdint>

// ---------------------------------------------------------------------------
// GraphSAGE (2x SAGEConv mean-agg + ReLU) + classifier, fp16 HMMA edition.
//   C = (Ah + Al) @ W_fp16  (A hi/lo split as K-expansion, W quantized once)
// 10-kernel pipeline:
//   1 k_front   : count_deg + convertX(hi/lo) + prepW   (fused)
//   2-4 scan1/2/3 : multi-block exclusive scan (coalesced) + sentinel
//   5 k_scatter : CSR fill + re-zero deg for next replay (fused)
//   6 k_agg L1, 7 gemm L1, 8 k_agg L2, 9 gemm L2, 10 gemm classifier
// ---------------------------------------------------------------------------

#define NN 100000
#define NE 1600000
#define F 128
#define MROWS 100096  // 782 * 128

// ------------------------- device scratch ---------------------------------
__device__ int g_deg[NN];         // zeroed at end of CSR build each replay
__device__ int g_rowoff[NN + 1];
__device__ int g_cursor[NN];
__device__ int g_csr[NE];
__device__ int g_blocksums[128];
__device__ int g_blockoffs[128];
__device__ __half g_A1[(size_t)MROWS * 512];  // [Xh|Xl|Gh|Gl]; reused as classifier A' (stride 256)
__device__ __half g_A2[(size_t)MROWS * 512];  // [Hh|Hl|Gh|Gl]
__device__ __half g_B1[128 * 256];            // [Ws1|Wn1] n-major
__device__ __half g_B2[128 * 256];            // [Ws2|Wn2]
__device__ __half g_Bc[64 * 128];             // Wo

// chunk tables
__constant__ int c_aL[8] = {0, 1, 2, 3, 4, 5, 6, 7};
__constant__ int c_bL[8] = {0, 1, 0, 1, 2, 3, 2, 3};
__constant__ int c_aK[4] = {0, 1, 2, 3};
__constant__ int c_bK[4] = {0, 1, 0, 1};

// ------------------------- PTX helpers ------------------------------------
__device__ __forceinline__ uint32_t smem_u32(const void* p) {
    uint32_t a;
    asm("{ .reg .u64 t; cvta.to.shared.u64 t, %1; cvt.u32.u64 %0, t; }"
        : "=r"(a) : "l"(p));
    return a;
}
__device__ __forceinline__ void cp16(uint32_t s, const void* g) {
    asm volatile("cp.async.cg.shared.global [%0], [%1], 16;" :: "r"(s), "l"(g) : "memory");
}
#define CP_COMMIT() asm volatile("cp.async.commit_group;" ::: "memory")
#define CP_WAIT(n)  asm volatile("cp.async.wait_group %0;" :: "n"(n) : "memory")

__device__ __forceinline__ void ldmx4(uint32_t a, uint32_t& r0, uint32_t& r1,
                                      uint32_t& r2, uint32_t& r3) {
    asm volatile("ldmatrix.sync.aligned.m8n8.x4.shared.b16 {%0,%1,%2,%3}, [%4];"
                 : "=r"(r0), "=r"(r1), "=r"(r2), "=r"(r3) : "r"(a));
}
__device__ __forceinline__ void mma16816(float* c, uint32_t a0, uint32_t a1,
                                         uint32_t a2, uint32_t a3,
                                         uint32_t b0, uint32_t b1) {
    asm volatile("mma.sync.aligned.m16n8k16.row.col.f32.f16.f16.f32 "
                 "{%0,%1,%2,%3}, {%4,%5,%6,%7}, {%8,%9}, {%0,%1,%2,%3};"
                 : "+f"(c[0]), "+f"(c[1]), "+f"(c[2]), "+f"(c[3])
                 : "r"(a0), "r"(a1), "r"(a2), "r"(a3), "r"(b0), "r"(b1));
}
__device__ __forceinline__ void split2(float v0, float v1, uint32_t& hi, uint32_t& lo) {
    __half h0 = __float2half_rn(v0), h1 = __float2half_rn(v1);
    __half l0 = __float2half_rn(v0 - __half2float(h0));
    __half l1 = __float2half_rn(v1 - __half2float(h1));
    __half2 hh = __halves2half2(h0, h1), ll = __halves2half2(l0, l1);
    hi = *reinterpret_cast<uint32_t*>(&hh);
    lo = *reinterpret_cast<uint32_t*>(&ll);
}

// ------------------------- 1) fused front kernel ---------------------------
__global__ void k_front(const int* __restrict__ dst,
                        const float* __restrict__ x, __half* __restrict__ A,
                        const float* __restrict__ Ws1, const float* __restrict__ Wn1,
                        const float* __restrict__ Ws2, const float* __restrict__ Wn2,
                        const float* __restrict__ Wo) {
    int idx = blockIdx.x * blockDim.x + threadIdx.x;
    if (idx < NE) atomicAdd(&g_deg[dst[idx]], 1);
    if (idx < NN * 32) {
        int row = idx >> 5;
        int c = (idx & 31) << 2;
        float4 v = *reinterpret_cast<const float4*>(x + (size_t)row * F + c);
        uint2 hi, lo;
        split2(v.x, v.y, hi.x, lo.x);
        split2(v.z, v.w, hi.y, lo.y);
        *reinterpret_cast<uint2*>(A + (size_t)row * 512 + c) = hi;        // Xh
        *reinterpret_cast<uint2*>(A + (size_t)row * 512 + 128 + c) = lo;  // Xl
    }
    if (idx < 16384) {
        int k = idx >> 7, n = idx & 127;
        g_B1[n * 256 + k]       = __float2half_rn(Ws1[k * 128 + n]);
        g_B1[n * 256 + 128 + k] = __float2half_rn(Wn1[k * 128 + n]);
        g_B2[n * 256 + k]       = __float2half_rn(Ws2[k * 128 + n]);
        g_B2[n * 256 + 128 + k] = __float2half_rn(Wn2[k * 128 + n]);
        if (n < 64) g_Bc[n * 128 + k] = __float2half_rn(Wo[k * 64 + n]);
    }
}

// ------------------------- 2-4) multi-block scan ----------------------------
__global__ void k_scan1(int n) {
    __shared__ int s[1024];
    int i = blockIdx.x * 1024 + threadIdx.x;
    int v = (i < n) ? g_deg[i] : 0;
    s[threadIdx.x] = v;
    __syncthreads();
#pragma unroll
    for (int off = 1; off < 1024; off <<= 1) {
        int t = (threadIdx.x >= off) ? s[threadIdx.x - off] : 0;
        __syncthreads();
        s[threadIdx.x] += t;
        __syncthreads();
    }
    if (i < n) g_rowoff[i] = s[threadIdx.x] - v;
    if (threadIdx.x == 1023) g_blocksums[blockIdx.x] = s[1023];
}
__global__ void k_scan2(int nb) {
    __shared__ int s[128];
    int v = (threadIdx.x < nb) ? g_blocksums[threadIdx.x] : 0;
    s[threadIdx.x] = v;
    __syncthreads();
#pragma unroll
    for (int off = 1; off < 128; off <<= 1) {
        int t = (threadIdx.x >= off) ? s[threadIdx.x - off] : 0;
        __syncthreads();
        s[threadIdx.x] += t;
        __syncthreads();
    }
    if (threadIdx.x < nb) g_blockoffs[threadIdx.x] = s[threadIdx.x] - v;
}
__global__ void k_scan3(int n) {
    int i = blockIdx.x * 1024 + threadIdx.x;
    if (i < n) {
        int r = g_rowoff[i] + g_blockoffs[blockIdx.x];
        g_rowoff[i] = r;
        g_cursor[i] = r;
        if (i == n - 1) g_rowoff[n] = r + g_deg[i];  // sentinel = NE
    }
}

// ------------------------- 5) scatter + deg re-zero -------------------------
__global__ void k_scatter(const int* __restrict__ src, const int* __restrict__ dst, int e) {
    int i = blockIdx.x * blockDim.x + threadIdx.x;
    if (i < e) {
        int d = dst[i];
        int pos = atomicAdd(&g_cursor[d], 1);
        g_csr[pos] = src[i];
    }
    if (i < NN) g_deg[i] = 0;  // clean for next graph replay (zero-init on 1st)
}

// ------------------------- 6/8) aggregation (warp per node, hi-only) -------
__global__ void k_agg(const __half* __restrict__ Hsrc, __half* __restrict__ Adst) {
    int node = (blockIdx.x * blockDim.x + threadIdx.x) >> 5;
    if (node >= NN) return;
    int lane = threadIdx.x & 31;
    int start = __ldg(&g_rowoff[node]);
    int cnt = __ldg(&g_rowoff[node + 1]) - start;
    float a0 = 0.f, a1 = 0.f, a2 = 0.f, a3 = 0.f;
    for (int j = 0; j < cnt; j += 32) {
        int myi = (j + lane < cnt) ? __ldg(&g_csr[start + j + lane]) : 0;
        int nj = min(32, cnt - j);
        int k = 0;
        for (; k + 4 <= nj; k += 4) {
            int s0 = __shfl_sync(0xffffffffu, myi, k);
            int s1 = __shfl_sync(0xffffffffu, myi, k + 1);
            int s2 = __shfl_sync(0xffffffffu, myi, k + 2);
            int s3 = __shfl_sync(0xffffffffu, myi, k + 3);
            uint2 u0 = *reinterpret_cast<const uint2*>(Hsrc + (size_t)s0 * 512 + (lane << 2));
            uint2 u1 = *reinterpret_cast<const uint2*>(Hsrc + (size_t)s1 * 512 + (lane << 2));
            uint2 u2 = *reinterpret_cast<const uint2*>(Hsrc + (size_t)s2 * 512 + (lane << 2));
            uint2 u3 = *reinterpret_cast<const uint2*>(Hsrc + (size_t)s3 * 512 + (lane << 2));
            float2 p0 = __half22float2(*reinterpret_cast<__half2*>(&u0.x));
            float2 p1 = __half22float2(*reinterpret_cast<__half2*>(&u0.y));
            float2 q0 = __half22float2(*reinterpret_cast<__half2*>(&u1.x));
            float2 q1 = __half22float2(*reinterpret_cast<__half2*>(&u1.y));
            float2 r0 = __half22float2(*reinterpret_cast<__half2*>(&u2.x));
            float2 r1 = __half22float2(*reinterpret_cast<__half2*>(&u2.y));
            float2 t0 = __half22float2(*reinterpret_cast<__half2*>(&u3.x));
            float2 t1 = __half22float2(*reinterpret_cast<__half2*>(&u3.y));
            a0 += (p0.x + q0.x) + (r0.x + t0.x);
            a1 += (p0.y + q0.y) + (r0.y + t0.y);
            a2 += (p1.x + q1.x) + (r1.x + t1.x);
            a3 += (p1.y + q1.y) + (r1.y + t1.y);
        }
        for (; k < nj; k++) {
            int s = __shfl_sync(0xffffffffu, myi, k);
            uint2 u = *reinterpret_cast<const uint2*>(Hsrc + (size_t)s * 512 + (lane << 2));
            float2 p0 = __half22float2(*reinterpret_cast<__half2*>(&u.x));
            float2 p1 = __half22float2(*reinterpret_cast<__half2*>(&u.y));
            a0 += p0.x; a1 += p0.y; a2 += p1.x; a3 += p1.y;
        }
    }
    float inv = (cnt > 0) ? (1.0f / (float)cnt) : 1.0f;
    a0 *= inv; a1 *= inv; a2 *= inv; a3 *= inv;
    uint2 hi, lo;
    split2(a0, a1, hi.x, lo.x);
    split2(a2, a3, hi.y, lo.y);
    *reinterpret_cast<uint2*>(Adst + (size_t)node * 512 + 256 + (lane << 2)) = hi;
    *reinterpret_cast<uint2*>(Adst + (size_t)node * 512 + 384 + (lane << 2)) = lo;
}

// ------------------------- warp-MMA GEMM -----------------------------------
template <int N, int NIT, int NBCH, int ASTR, int BSTR, int EPI, int OSTR>
__global__ __launch_bounds__(256) void k_gemm_mma(
    const __half* __restrict__ A, const __half* __restrict__ B,
    const float* __restrict__ bias, float* __restrict__ outF,
    __half* __restrict__ outA, int M)
{
    constexpr int WM = (N == 128) ? 2 : 1;
    constexpr int AT = 128 * 128;        // bytes per A stage
    constexpr int BT = N * 128;          // bytes per B chunk
    extern __shared__ char smem[];
    float* s_bias = reinterpret_cast<float*>(smem);
    const uint32_t sA0 = smem_u32(smem + 512);
    const uint32_t sB0 = sA0 + 2 * AT;

    const int tid = threadIdx.x;
    const int wid = tid >> 5, lane = tid & 31;
    const int wm = (N == 128) ? (wid >> 1) : wid;
    const int wn = (N == 128) ? (wid & 1) : 0;
    const int row0 = blockIdx.x * 128;

    if (tid < N) s_bias[tid] = bias[tid];

    const int* aC = (NIT == 8) ? c_aL : c_aK;
    const int* bC = (NIT == 8) ? c_bL : c_bK;
    const char* Ab = reinterpret_cast<const char*>(A);
    const char* Bb = reinterpret_cast<const char*>(B);
    const int g = lane >> 3, lr = lane & 7;

    float acc[WM][8][4];
#pragma unroll
    for (int i = 0; i < WM; i++)
#pragma unroll
        for (int j = 0; j < 8; j++)
#pragma unroll
            for (int k = 0; k < 4; k++) acc[i][j][k] = 0.f;

    auto load_A = [&](int i) {
        const uint32_t sa = sA0 + (i & 1) * AT;
        const int ca = aC[i];
#pragma unroll
        for (int t = 0; t < 4; t++) {
            int idx = tid + t * 256;
            int m = idx >> 3, u = idx & 7;
            int r = row0 + m; if (r >= M) r = M - 1;
            cp16(sa + m * 128 + ((u ^ (m & 7)) << 4),
                 Ab + ((size_t)r * ASTR + ca * 64 + u * 8) * 2);
        }
        CP_COMMIT();
    };

    // prologue: all of B, committed together with A chunk 0
    {
        constexpr int TOT = NBCH * N * 8;
#pragma unroll
        for (int t = 0; t < TOT / 256; t++) {
            int idx = tid + t * 256;
            int ch = idx / (N * 8);
            int rem = idx % (N * 8);
            int n = rem >> 3, u = rem & 7;
            cp16(sB0 + ch * BT + n * 128 + ((u ^ (n & 7)) << 4),
                 Bb + ((size_t)n * BSTR + ch * 64 + u * 8) * 2);
        }
    }
    load_A(0);

    for (int i = 0; i < NIT; i++) {
        if (i + 1 < NIT) { load_A(i + 1); CP_WAIT(1); }
        else { CP_WAIT(0); }
        __syncthreads();
        const uint32_t sa = sA0 + (i & 1) * AT;
        const uint32_t sbb = sB0 + bC[i] * BT;
#pragma unroll
        for (int kk = 0; kk < 4; kk++) {
            uint32_t a[WM][4];
#pragma unroll
            for (int mt = 0; mt < WM; mt++) {
                int row = wm * (WM * 16) + mt * 16 + (g & 1) * 8 + lr;
                int u = kk * 2 + (g >> 1);
                ldmx4(sa + row * 128 + ((u ^ (row & 7)) << 4),
                      a[mt][0], a[mt][1], a[mt][2], a[mt][3]);
            }
            uint32_t b[4][4];
#pragma unroll
            for (int j = 0; j < 4; j++) {
                int n = wn * 64 + j * 16 + (g >> 1) * 8 + lr;
                int u = kk * 2 + (g & 1);
                ldmx4(sbb + n * 128 + ((u ^ (n & 7)) << 4),
                      b[j][0], b[j][1], b[j][2], b[j][3]);
            }
#pragma unroll
            for (int mt = 0; mt < WM; mt++)
#pragma unroll
                for (int nt = 0; nt < 8; nt++)
                    mma16816(acc[mt][nt],
                             a[mt][0], a[mt][1], a[mt][2], a[mt][3],
                             b[nt >> 1][(nt & 1) * 2], b[nt >> 1][(nt & 1) * 2 + 1]);
        }
        __syncthreads();
    }

    // epilogue
    const int qr = lane >> 2, qc = (lane & 3) << 1;
#pragma unroll
    for (int mt = 0; mt < WM; mt++) {
#pragma unroll
        for (int h = 0; h < 2; h++) {
            int row = row0 + wm * (WM * 16) + mt * 16 + h * 8 + qr;
            if (row >= M) continue;
#pragma unroll
            for (int nt = 0; nt < 8; nt++) {
                int col = wn * 64 + nt * 8 + qc;
                float v0 = acc[mt][nt][h * 2 + 0] + s_bias[col];
                float v1 = acc[mt][nt][h * 2 + 1] + s_bias[col + 1];
                if (EPI == 1) {
                    v0 = fmaxf(v0, 0.f); v1 = fmaxf(v1, 0.f);
                    uint32_t hi, lo;
                    split2(v0, v1, hi, lo);
                    *reinterpret_cast<uint32_t*>(outA + (size_t)row * OSTR + col) = hi;
                    *reinterpret_cast<uint32_t*>(outA + (size_t)row * OSTR + 128 + col) = lo;
                } else {
                    float2 f2 = {v0, v1};
                    *reinterpret_cast<float2*>(outF + (size_t)row * 64 + col) = f2;
                }
            }
        }
    }
}

// ------------------------- launch ------------------------------------------
extern "C" void kernel_launch(void* const* d_in, const int* in_sizes, int n_in,
                              void* d_out, int out_size) {
    const float* x       = (const float*)d_in[0];
    const float* Wself1  = (const float*)d_in[1];
    const float* Wneigh1 = (const float*)d_in[2];
    const float* b1      = (const float*)d_in[3];
    const float* Wself2  = (const float*)d_in[4];
    const float* Wneigh2 = (const float*)d_in[5];
    const float* b2      = (const float*)d_in[6];
    const float* Wout    = (const float*)d_in[7];
    const float* bout    = (const float*)d_in[8];
    const int* edge_src  = (const int*)d_in[9];
    const int* edge_dst  = (const int*)d_in[10];
    float* out = (float*)d_out;

    const int M = in_sizes[0] / F;      // 100000
    const int E = in_sizes[9];          // 1600000
    const int NB = (M + 1023) / 1024;   // 98
    const int GB = (M + 127) / 128;     // 782
    const int AGGB = (M * 32 + 255) / 256;
    const int FRONTB = (NN * 32 + 255) / 256;

    __half *A1, *A2, *B1, *B2, *Bc;
    cudaGetSymbolAddress((void**)&A1, g_A1);
    cudaGetSymbolAddress((void**)&A2, g_A2);
    cudaGetSymbolAddress((void**)&B1, g_B1);
    cudaGetSymbolAddress((void**)&B2, g_B2);
    cudaGetSymbolAddress((void**)&Bc, g_Bc);

    const int SMEM_L = 512 + 2 * 16384 + 4 * 128 * 128;  // 98816
    const int SMEM_C = 512 + 2 * 16384 + 2 * 64 * 128;   // 49664
    cudaFuncSetAttribute((const void*)k_gemm_mma<128, 8, 4, 512, 256, 1, 512>,
                         cudaFuncAttributeMaxDynamicSharedMemorySize, SMEM_L);
    cudaFuncSetAttribute((const void*)k_gemm_mma<128, 8, 4, 512, 256, 1, 256>,
                         cudaFuncAttributeMaxDynamicSharedMemorySize, SMEM_L);
    cudaFuncSetAttribute((const void*)k_gemm_mma<64, 4, 2, 256, 128, 2, 0>,
                         cudaFuncAttributeMaxDynamicSharedMemorySize, SMEM_C);

    // 1) fused: degree count + X hi/lo convert + weight prep
    k_front<<<FRONTB, 256>>>(edge_dst, x, A1, Wself1, Wneigh1, Wself2, Wneigh2, Wout);
    // 2-4) multi-block exclusive scan (coalesced)
    k_scan1<<<NB, 1024>>>(M);
    k_scan2<<<1, 128>>>(NB);
    k_scan3<<<NB, 1024>>>(M);
    // 5) CSR scatter + deg re-zero
    k_scatter<<<(E + 255) / 256, 256>>>(edge_src, edge_dst, E);
    // 6) layer-1 aggregation
    k_agg<<<AGGB, 256>>>(A1, A1);
    // 7) layer-1 GEMM -> A2 [Hh|Hl]
    k_gemm_mma<128, 8, 4, 512, 256, 1, 512><<<GB, 256, SMEM_L>>>(A1, B1, b1, nullptr, A2, M);
    // 8) layer-2 aggregation
    k_agg<<<AGGB, 256>>>(A2, A2);
    // 9) layer-2 GEMM -> classifier A' in A1 (stride 256)
    k_gemm_mma<128, 8, 4, 512, 256, 1, 256><<<GB, 256, SMEM_L>>>(A2, B2, b2, nullptr, A1, M);
    // 10) classifier
    k_gemm_mma<64, 4, 2, 256, 128, 2, 0><<<GB, 256, SMEM_C>>>(A1, Bc, bout, out, nullptr, M);
}

// round 8
// speedup vs baseline: 1.9897x; 1.2881x over previous
#include <cuda_runtime.h>
#include <cuda_fp16.h>
#include <cstdint>

// ---------------------------------------------------------------------------
// GraphSAGE (2x SAGEConv mean-agg + ReLU) + classifier, fp16 HMMA edition.
//   C = A_fp16 @ W_fp16 (fp32 accumulate), single-term quantization.
// A'[M,256] = [Xh|Gh] (layer), [Hh] cols 0-127 (classifier), stride 256.
// 10-kernel pipeline: front / scan1/2/3 / scatter / agg / gemm / agg / gemm / gemm.
// ---------------------------------------------------------------------------

#define NN 100000
#define NE 1600000
#define F 128
#define MROWS 100096  // 782 * 128

// ------------------------- device scratch ---------------------------------
__device__ int g_deg[NN];         // re-zeroed by k_scatter each replay
__device__ int g_rowoff[NN + 1];
__device__ int g_cursor[NN];
__device__ int g_csr[NE];
__device__ int g_blocksums[128];
__device__ int g_blockoffs[128];
__device__ __half g_A1[(size_t)MROWS * 256];  // [Xh|Gh]; later [Hh2|..] for classifier
__device__ __half g_A2[(size_t)MROWS * 256];  // [Hh|Gh]
__device__ __half g_B1[128 * 256];            // [Ws1|Wn1] n-major (k contiguous)
__device__ __half g_B2[128 * 256];            // [Ws2|Wn2]
__device__ __half g_Bc[64 * 128];             // Wo

// ------------------------- PTX helpers ------------------------------------
__device__ __forceinline__ uint32_t smem_u32(const void* p) {
    uint32_t a;
    asm("{ .reg .u64 t; cvta.to.shared.u64 t, %1; cvt.u32.u64 %0, t; }"
        : "=r"(a) : "l"(p));
    return a;
}
__device__ __forceinline__ void cp16(uint32_t s, const void* g) {
    asm volatile("cp.async.cg.shared.global [%0], [%1], 16;" :: "r"(s), "l"(g) : "memory");
}
#define CP_COMMIT() asm volatile("cp.async.commit_group;" ::: "memory")
#define CP_WAIT(n)  asm volatile("cp.async.wait_group %0;" :: "n"(n) : "memory")

__device__ __forceinline__ void ldmx4(uint32_t a, uint32_t& r0, uint32_t& r1,
                                      uint32_t& r2, uint32_t& r3) {
    asm volatile("ldmatrix.sync.aligned.m8n8.x4.shared.b16 {%0,%1,%2,%3}, [%4];"
                 : "=r"(r0), "=r"(r1), "=r"(r2), "=r"(r3) : "r"(a));
}
__device__ __forceinline__ void mma16816(float* c, uint32_t a0, uint32_t a1,
                                         uint32_t a2, uint32_t a3,
                                         uint32_t b0, uint32_t b1) {
    asm volatile("mma.sync.aligned.m16n8k16.row.col.f32.f16.f16.f32 "
                 "{%0,%1,%2,%3}, {%4,%5,%6,%7}, {%8,%9}, {%0,%1,%2,%3};"
                 : "+f"(c[0]), "+f"(c[1]), "+f"(c[2]), "+f"(c[3])
                 : "r"(a0), "r"(a1), "r"(a2), "r"(a3), "r"(b0), "r"(b1));
}

// ------------------------- 1) fused front kernel ---------------------------
// count_deg (idx < NE) + convertX hi (idx < NN*32) + prepW (idx < 16384)
__global__ void k_front(const int* __restrict__ dst,
                        const float* __restrict__ x, __half* __restrict__ A,
                        const float* __restrict__ Ws1, const float* __restrict__ Wn1,
                        const float* __restrict__ Ws2, const float* __restrict__ Wn2,
                        const float* __restrict__ Wo) {
    int idx = blockIdx.x * blockDim.x + threadIdx.x;
    if (idx < NE) atomicAdd(&g_deg[dst[idx]], 1);
    if (idx < NN * 32) {
        int row = idx >> 5;
        int c = (idx & 31) << 2;
        float4 v = *reinterpret_cast<const float4*>(x + (size_t)row * F + c);
        __half2 ha = __floats2half2_rn(v.x, v.y);
        __half2 hb = __floats2half2_rn(v.z, v.w);
        uint2 o;
        o.x = *reinterpret_cast<uint32_t*>(&ha);
        o.y = *reinterpret_cast<uint32_t*>(&hb);
        *reinterpret_cast<uint2*>(A + (size_t)row * 256 + c) = o;  // Xh
    }
    if (idx < 16384) {
        int k = idx >> 7, n = idx & 127;
        g_B1[n * 256 + k]       = __float2half_rn(Ws1[k * 128 + n]);
        g_B1[n * 256 + 128 + k] = __float2half_rn(Wn1[k * 128 + n]);
        g_B2[n * 256 + k]       = __float2half_rn(Ws2[k * 128 + n]);
        g_B2[n * 256 + 128 + k] = __float2half_rn(Wn2[k * 128 + n]);
        if (n < 64) g_Bc[n * 128 + k] = __float2half_rn(Wo[k * 64 + n]);
    }
}

// ------------------------- 2-4) multi-block scan ----------------------------
__global__ void k_scan1(int n) {
    __shared__ int s[1024];
    int i = blockIdx.x * 1024 + threadIdx.x;
    int v = (i < n) ? g_deg[i] : 0;
    s[threadIdx.x] = v;
    __syncthreads();
#pragma unroll
    for (int off = 1; off < 1024; off <<= 1) {
        int t = (threadIdx.x >= off) ? s[threadIdx.x - off] : 0;
        __syncthreads();
        s[threadIdx.x] += t;
        __syncthreads();
    }
    if (i < n) g_rowoff[i] = s[threadIdx.x] - v;
    if (threadIdx.x == 1023) g_blocksums[blockIdx.x] = s[1023];
}
__global__ void k_scan2(int nb) {
    __shared__ int s[128];
    int v = (threadIdx.x < nb) ? g_blocksums[threadIdx.x] : 0;
    s[threadIdx.x] = v;
    __syncthreads();
#pragma unroll
    for (int off = 1; off < 128; off <<= 1) {
        int t = (threadIdx.x >= off) ? s[threadIdx.x - off] : 0;
        __syncthreads();
        s[threadIdx.x] += t;
        __syncthreads();
    }
    if (threadIdx.x < nb) g_blockoffs[threadIdx.x] = s[threadIdx.x] - v;
}
__global__ void k_scan3(int n) {
    int i = blockIdx.x * 1024 + threadIdx.x;
    if (i < n) {
        int r = g_rowoff[i] + g_blockoffs[blockIdx.x];
        g_rowoff[i] = r;
        g_cursor[i] = r;
        if (i == n - 1) g_rowoff[n] = r + g_deg[i];  // sentinel = NE
    }
}

// ------------------------- 5) scatter + deg re-zero -------------------------
__global__ void k_scatter(const int* __restrict__ src, const int* __restrict__ dst, int e) {
    int i = blockIdx.x * blockDim.x + threadIdx.x;
    if (i < e) {
        int d = dst[i];
        int pos = atomicAdd(&g_cursor[d], 1);
        g_csr[pos] = src[i];
    }
    if (i < NN) g_deg[i] = 0;
}

// ------------------------- 6/8) aggregation (paired-edge warp gather) ------
// Reads hi row (offset 0, stride 256 halves, 256B) of Hsrc.
// Half-warps take alternate edges; each lane loads uint4 (8 halves = 8 dims).
// Cross-half shfl_xor(16) reduce; lanes 0-15 write Gh at col 128 (16B each).
__global__ void k_agg(const __half* __restrict__ Hsrc, __half* __restrict__ Adst) {
    int node = (blockIdx.x * blockDim.x + threadIdx.x) >> 5;
    if (node >= NN) return;
    const int lane = threadIdx.x & 31;
    const int hw = lane >> 4;        // 0 or 1
    const int sub = lane & 15;       // dim group: dims [sub*8, sub*8+8)
    int start = __ldg(&g_rowoff[node]);
    int cnt = __ldg(&g_rowoff[node + 1]) - start;
    float a[8];
#pragma unroll
    for (int t = 0; t < 8; t++) a[t] = 0.f;

    for (int j = 0; j < cnt; j += 32) {
        int myi = (j + lane < cnt) ? __ldg(&g_csr[start + j + lane]) : 0;
        int nj = min(32, cnt - j);
        int k = 0;
        for (; k + 4 <= nj; k += 4) {
            int s0 = __shfl_sync(0xffffffffu, myi, k + hw);
            int s1 = __shfl_sync(0xffffffffu, myi, k + 2 + hw);
            uint4 u0 = *reinterpret_cast<const uint4*>(Hsrc + (size_t)s0 * 256 + (sub << 3));
            uint4 u1 = *reinterpret_cast<const uint4*>(Hsrc + (size_t)s1 * 256 + (sub << 3));
#pragma unroll
            for (int q = 0; q < 4; q++) {
                uint32_t w0 = (&u0.x)[q], w1 = (&u1.x)[q];
                float2 f0 = __half22float2(*reinterpret_cast<__half2*>(&w0));
                float2 f1 = __half22float2(*reinterpret_cast<__half2*>(&w1));
                a[q * 2 + 0] += f0.x + f1.x;
                a[q * 2 + 1] += f0.y + f1.y;
            }
        }
        for (; k + 2 <= nj; k += 2) {
            int s = __shfl_sync(0xffffffffu, myi, k + hw);
            uint4 u = *reinterpret_cast<const uint4*>(Hsrc + (size_t)s * 256 + (sub << 3));
#pragma unroll
            for (int q = 0; q < 4; q++) {
                uint32_t w = (&u.x)[q];
                float2 f = __half22float2(*reinterpret_cast<__half2*>(&w));
                a[q * 2 + 0] += f.x;
                a[q * 2 + 1] += f.y;
            }
        }
        if (k < nj) {
            int s = __shfl_sync(0xffffffffu, myi, k);
            if (hw == 0) {
                uint4 u = *reinterpret_cast<const uint4*>(Hsrc + (size_t)s * 256 + (sub << 3));
#pragma unroll
                for (int q = 0; q < 4; q++) {
                    uint32_t w = (&u.x)[q];
                    float2 f = __half22float2(*reinterpret_cast<__half2*>(&w));
                    a[q * 2 + 0] += f.x;
                    a[q * 2 + 1] += f.y;
                }
            }
        }
    }
#pragma unroll
    for (int t = 0; t < 8; t++) a[t] += __shfl_xor_sync(0xffffffffu, a[t], 16);
    if (hw == 0) {
        float inv = (cnt > 0) ? (1.0f / (float)cnt) : 1.0f;
        uint4 o;
#pragma unroll
        for (int q = 0; q < 4; q++) {
            __half2 h = __floats2half2_rn(a[q * 2] * inv, a[q * 2 + 1] * inv);
            (&o.x)[q] = *reinterpret_cast<uint32_t*>(&h);
        }
        *reinterpret_cast<uint4*>(Adst + (size_t)node * 256 + 128 + (sub << 3)) = o;
    }
}

// ------------------------- warp-MMA GEMM -----------------------------------
// D[128, N] = sum over NIT K=64 chunks (identity chunk map) + bias (+relu).
// All of B resident in smem (NIT chunks); A double-buffered via cp.async.
// EPI: 1 = relu, fp16 hi to outA (row stride OSTR)
//      2 = none, fp32 to outF (row stride 64)
template <int N, int NIT, int ASTR, int BSTR, int EPI, int OSTR>
__global__ __launch_bounds__(256) void k_gemm_mma(
    const __half* __restrict__ A, const __half* __restrict__ B,
    const float* __restrict__ bias, float* __restrict__ outF,
    __half* __restrict__ outA, int M)
{
    constexpr int WM = (N == 128) ? 2 : 1;
    constexpr int AT = 128 * 128;        // bytes per A stage
    constexpr int BT = N * 128;          // bytes per B chunk
    extern __shared__ char smem[];
    float* s_bias = reinterpret_cast<float*>(smem);
    const uint32_t sA0 = smem_u32(smem + 512);
    const uint32_t sB0 = sA0 + 2 * AT;

    const int tid = threadIdx.x;
    const int wid = tid >> 5, lane = tid & 31;
    const int wm = (N == 128) ? (wid >> 1) : wid;
    const int wn = (N == 128) ? (wid & 1) : 0;
    const int row0 = blockIdx.x * 128;

    if (tid < N) s_bias[tid] = bias[tid];

    const char* Ab = reinterpret_cast<const char*>(A);
    const char* Bb = reinterpret_cast<const char*>(B);
    const int g = lane >> 3, lr = lane & 7;

    float acc[WM][8][4];
#pragma unroll
    for (int i = 0; i < WM; i++)
#pragma unroll
        for (int j = 0; j < 8; j++)
#pragma unroll
            for (int k = 0; k < 4; k++) acc[i][j][k] = 0.f;

    auto load_A = [&](int i) {
        const uint32_t sa = sA0 + (i & 1) * AT;
#pragma unroll
        for (int t = 0; t < 4; t++) {
            int idx = tid + t * 256;
            int m = idx >> 3, u = idx & 7;
            int r = row0 + m; if (r >= M) r = M - 1;
            cp16(sa + m * 128 + ((u ^ (m & 7)) << 4),
                 Ab + ((size_t)r * ASTR + i * 64 + u * 8) * 2);
        }
        CP_COMMIT();
    };

    // prologue: all of B, committed together with A chunk 0
    {
        constexpr int TOT = NIT * N * 8;
#pragma unroll
        for (int t = 0; t < TOT / 256; t++) {
            int idx = tid + t * 256;
            int ch = idx / (N * 8);
            int rem = idx % (N * 8);
            int n = rem >> 3, u = rem & 7;
            cp16(sB0 + ch * BT + n * 128 + ((u ^ (n & 7)) << 4),
                 Bb + ((size_t)n * BSTR + ch * 64 + u * 8) * 2);
        }
    }
    load_A(0);

    for (int i = 0; i < NIT; i++) {
        if (i + 1 < NIT) { load_A(i + 1); CP_WAIT(1); }
        else { CP_WAIT(0); }
        __syncthreads();
        const uint32_t sa = sA0 + (i & 1) * AT;
        const uint32_t sbb = sB0 + i * BT;
#pragma unroll
        for (int kk = 0; kk < 4; kk++) {
            uint32_t a[WM][4];
#pragma unroll
            for (int mt = 0; mt < WM; mt++) {
                int row = wm * (WM * 16) + mt * 16 + (g & 1) * 8 + lr;
                int u = kk * 2 + (g >> 1);
                ldmx4(sa + row * 128 + ((u ^ (row & 7)) << 4),
                      a[mt][0], a[mt][1], a[mt][2], a[mt][3]);
            }
            uint32_t b[4][4];
#pragma unroll
            for (int j = 0; j < 4; j++) {
                int n = wn * 64 + j * 16 + (g >> 1) * 8 + lr;
                int u = kk * 2 + (g & 1);
                ldmx4(sbb + n * 128 + ((u ^ (n & 7)) << 4),
                      b[j][0], b[j][1], b[j][2], b[j][3]);
            }
#pragma unroll
            for (int mt = 0; mt < WM; mt++)
#pragma unroll
                for (int nt = 0; nt < 8; nt++)
                    mma16816(acc[mt][nt],
                             a[mt][0], a[mt][1], a[mt][2], a[mt][3],
                             b[nt >> 1][(nt & 1) * 2], b[nt >> 1][(nt & 1) * 2 + 1]);
        }
        __syncthreads();
    }

    // epilogue
    const int qr = lane >> 2, qc = (lane & 3) << 1;
#pragma unroll
    for (int mt = 0; mt < WM; mt++) {
#pragma unroll
        for (int h = 0; h < 2; h++) {
            int row = row0 + wm * (WM * 16) + mt * 16 + h * 8 + qr;
            if (row >= M) continue;
#pragma unroll
            for (int nt = 0; nt < 8; nt++) {
                int col = wn * 64 + nt * 8 + qc;
                float v0 = acc[mt][nt][h * 2 + 0] + s_bias[col];
                float v1 = acc[mt][nt][h * 2 + 1] + s_bias[col + 1];
                if (EPI == 1) {
                    v0 = fmaxf(v0, 0.f); v1 = fmaxf(v1, 0.f);
                    __half2 hh = __floats2half2_rn(v0, v1);
                    *reinterpret_cast<uint32_t*>(outA + (size_t)row * OSTR + col) =
                        *reinterpret_cast<uint32_t*>(&hh);
                } else {
                    float2 f2 = {v0, v1};
                    *reinterpret_cast<float2*>(outF + (size_t)row * 64 + col) = f2;
                }
            }
        }
    }
}

// ------------------------- launch ------------------------------------------
extern "C" void kernel_launch(void* const* d_in, const int* in_sizes, int n_in,
                              void* d_out, int out_size) {
    const float* x       = (const float*)d_in[0];
    const float* Wself1  = (const float*)d_in[1];
    const float* Wneigh1 = (const float*)d_in[2];
    const float* b1      = (const float*)d_in[3];
    const float* Wself2  = (const float*)d_in[4];
    const float* Wneigh2 = (const float*)d_in[5];
    const float* b2      = (const float*)d_in[6];
    const float* Wout    = (const float*)d_in[7];
    const float* bout    = (const float*)d_in[8];
    const int* edge_src  = (const int*)d_in[9];
    const int* edge_dst  = (const int*)d_in[10];
    float* out = (float*)d_out;

    const int M = in_sizes[0] / F;      // 100000
    const int E = in_sizes[9];          // 1600000
    const int NB = (M + 1023) / 1024;   // 98
    const int GB = (M + 127) / 128;     // 782
    const int AGGB = (M * 32 + 255) / 256;
    const int FRONTB = (NN * 32 + 255) / 256;

    __half *A1, *A2, *B1, *B2, *Bc;
    cudaGetSymbolAddress((void**)&A1, g_A1);
    cudaGetSymbolAddress((void**)&A2, g_A2);
    cudaGetSymbolAddress((void**)&B1, g_B1);
    cudaGetSymbolAddress((void**)&B2, g_B2);
    cudaGetSymbolAddress((void**)&Bc, g_Bc);

    const int SMEM_L = 512 + 2 * 16384 + 4 * 128 * 128;  // 98816
    const int SMEM_C = 512 + 2 * 16384 + 2 * 64 * 128;   // 49664
    cudaFuncSetAttribute((const void*)k_gemm_mma<128, 4, 256, 256, 1, 256>,
                         cudaFuncAttributeMaxDynamicSharedMemorySize, SMEM_L);
    cudaFuncSetAttribute((const void*)k_gemm_mma<64, 2, 256, 128, 2, 0>,
                         cudaFuncAttributeMaxDynamicSharedMemorySize, SMEM_C);

    // 1) fused: degree count + X hi convert + weight prep
    k_front<<<FRONTB, 256>>>(edge_dst, x, A1, Wself1, Wneigh1, Wself2, Wneigh2, Wout);
    // 2-4) multi-block exclusive scan (coalesced)
    k_scan1<<<NB, 1024>>>(M);
    k_scan2<<<1, 128>>>(NB);
    k_scan3<<<NB, 1024>>>(M);
    // 5) CSR scatter + deg re-zero
    k_scatter<<<(E + 255) / 256, 256>>>(edge_src, edge_dst, E);
    // 6) layer-1 aggregation: gather Xh from A1, write Gh into A1 col 128
    k_agg<<<AGGB, 256>>>(A1, A1);
    // 7) layer-1 GEMM -> Hh into A2 col 0 (stride 256)
    k_gemm_mma<128, 4, 256, 256, 1, 256><<<GB, 256, SMEM_L>>>(A1, B1, b1, nullptr, A2, M);
    // 8) layer-2 aggregation: gather Hh from A2, write Gh into A2 col 128
    k_agg<<<AGGB, 256>>>(A2, A2);
    // 9) layer-2 GEMM -> Hh2 into A1 col 0 (stride 256)
    k_gemm_mma<128, 4, 256, 256, 1, 256><<<GB, 256, SMEM_L>>>(A2, B2, b2, nullptr, A1, M);
    // 10) classifier (reads A1 cols 0-127, K=128)
    k_gemm_mma<64, 2, 256, 128, 2, 0><<<GB, 256, SMEM_C>>>(A1, Bc, bout, out, nullptr, M);
}